// round 15
// baseline (speedup 1.0000x reference)
#include <cuda_runtime.h>
#include <cuda_fp16.h>
#include <math.h>
#include <stdint.h>

// ---------------- problem dims ----------------
#define Bsz   16
#define Tsz   1000
#define Nsz   100
#define ENC   512
#define VOCABn 10025
#define EMB   640
#define HID   1024
#define ATT   1024
#define PROJ  1024
#define XIN   (EMB+ENC)      // 1152
#define ROK   (HID+EMB+ENC)  // 2176
#define ROWS  (Bsz*Nsz)      // 1600
#define GATES (4*HID)        // 4096

#define LOGITS_ELEMS ((size_t)ROWS*VOCABn)
#define TAIL_ELEMS   (2*Bsz*HID + Bsz*ENC + Bsz*Tsz)
#define INIT_ELEMS   (Bsz*HID > Bsz*Tsz ? Bsz*HID : Bsz*Tsz)   // 16384

#define PERSIST_BLOCKS 296   // 2 per SM x 148 SMs: co-residency guaranteed by __launch_bounds__(256,2)

// ---------------- device scratch ----------------
__device__ __align__(16) float g_emb[Bsz*Nsz*EMB];
__device__ __align__(16) __half g_enc_ctx[(size_t)Bsz*Tsz*ATT];   // 32.8 MB fp16 (R10-proven)
__device__ __align__(16) float g_gates_emb[(size_t)ROWS*GATES];   // W_ih-emb part + b_ih
__device__ __align__(16) float g_inv_fert[Bsz*Tsz];
__device__ __align__(16) float g_c[Bsz*HID];
__device__ __align__(16) float g_accum[Bsz*Tsz];
__device__ __align__(16) float g_s_t[Bsz*ATT];
__device__ __align__(16) float g_energies[Bsz*Tsz];
__device__ __align__(16) float g_s_stk[(size_t)Bsz*Nsz*HID];   // h per step (h double-buffer)
__device__ __align__(16) float g_ctx_stk[(size_t)Bsz*Nsz*ENC];
__device__ __align__(16) float g_ro_cat[(size_t)ROWS*ROK];
__device__ __align__(16) float g_ro_in[(size_t)ROWS*PROJ];
__device__ __align__(16) float g_readout[(size_t)ROWS*(PROJ/2)];

// grid barrier state (self-resetting: even barrier count per call -> returns to 0)
__device__ int g_bar_count;
__device__ int g_bar_sense;

// ---------------- helpers (accurate activation forms — proven) ----------------
__device__ __forceinline__ float sigf(float x) {
    return 1.0f / (1.0f + __expf(-x));
}
__device__ __forceinline__ float tanh_acc(float x) {
    float e = __expf(2.0f * x);
    return 1.0f - 2.0f / (e + 1.0f);
}
__device__ __forceinline__ float warp_sum(float v) {
    #pragma unroll
    for (int off = 16; off; off >>= 1) v += __shfl_xor_sync(0xffffffffu, v, off);
    return v;
}
__device__ __forceinline__ float dot4(float4 a, float4 b) {
    return a.x*b.x + a.y*b.y + a.z*b.z + a.w*b.w;
}
__device__ __forceinline__ float2 h22f2(unsigned v) {
    __half2 h = *reinterpret_cast<__half2*>(&v);
    return __half22float2(h);
}

// sense-reversing global barrier; all blocks of the persistent kernel call this.
__device__ __forceinline__ void grid_barrier(int* local_sense) {
    __syncthreads();
    if (threadIdx.x == 0) {
        int next = *local_sense ^ 1;
        __threadfence();
        int old = atomicAdd(&g_bar_count, 1);
        if (old == (int)gridDim.x - 1) {
            g_bar_count = 0;
            __threadfence();
            atomicExch(&g_bar_sense, next);
        } else {
            volatile int* vs = (volatile int*)&g_bar_sense;
            while (*vs != next) {}
            __threadfence();
        }
    }
    *local_sense ^= 1;
    __syncthreads();
}

// ---------------- init ----------------
__global__ void init_state_kernel() {
    int i = blockIdx.x * blockDim.x + threadIdx.x;
    if (i < Bsz*HID) g_c[i] = 0.0f;
    if (i < Bsz*Tsz) g_accum[i] = 0.0f;
}

// ---------------- shifted embedding gather (float4) ----------------
__global__ void embed_kernel(const int* __restrict__ labels,
                             const float4* __restrict__ table4) {
    int i = blockIdx.x * blockDim.x + threadIdx.x;
    if (i >= Bsz*Nsz*(EMB/4)) return;
    int k4 = i % (EMB/4);
    int r  = i / (EMB/4);
    int nn = r % Nsz;
    int b  = r / Nsz;
    float4 v = make_float4(0,0,0,0);
    if (nn > 0) {
        int lab = labels[b*Nsz + nn - 1];
        v = table4[(size_t)lab*(EMB/4) + k4];
    }
    ((float4*)g_emb)[i] = v;
}

// ---------------- inv_fertility ----------------
__global__ void fert_kernel(const float4* __restrict__ enc4,
                            const float4* __restrict__ Wf4) {
    int gw   = (blockIdx.x * blockDim.x + threadIdx.x) >> 5;
    int lane = threadIdx.x & 31;
    if (gw >= Bsz*Tsz) return;
    const float4* row = enc4 + (size_t)gw * (ENC/4);
    float s = 0.0f;
    #pragma unroll
    for (int it = 0; it < 4; it++) {
        int k4 = it*32 + lane;
        s += dot4(row[k4], Wf4[k4]);
    }
    s = warp_sum(s);
    if (lane == 0) g_inv_fert[gw] = sigf(s);
}

// ---------------- SGEMM (R8-proven, + lda/ldb): C[M,N] = A@B^T + bias ----------------
__device__ __forceinline__ void store_val(float* C, size_t i, float v) { C[i] = v; }
__device__ __forceinline__ void store_val(__half* C, size_t i, float v) { C[i] = __float2half_rn(v); }

template <typename OutT>
__global__ __launch_bounds__(256)
void gemm_tn_bias(const float* __restrict__ A, int lda,
                  const float* __restrict__ Bm, int ldb,
                  const float* __restrict__ bias, OutT* __restrict__ C,
                  int M, int N, int K)
{
    __shared__ float As[8][128];
    __shared__ float Bs[8][128];
    int tid = threadIdx.x;
    int m0 = blockIdx.y * 128;
    int n0 = blockIdx.x * 128;
    int tx = tid & 15, ty = tid >> 4;

    float acc[8][8];
    #pragma unroll
    for (int i = 0; i < 8; i++)
        #pragma unroll
        for (int j = 0; j < 8; j++) acc[i][j] = 0.0f;

    int ar = tid >> 1;
    int ak = (tid & 1) * 4;

    for (int k0 = 0; k0 < K; k0 += 8) {
        float4 av = make_float4(0,0,0,0), bv = make_float4(0,0,0,0);
        int gr = m0 + ar;
        if (gr < M) av = *(const float4*)(A + (size_t)gr * lda + k0 + ak);
        int gc = n0 + ar;
        if (gc < N) bv = *(const float4*)(Bm + (size_t)gc * ldb + k0 + ak);
        __syncthreads();
        As[ak+0][ar] = av.x; As[ak+1][ar] = av.y; As[ak+2][ar] = av.z; As[ak+3][ar] = av.w;
        Bs[ak+0][ar] = bv.x; Bs[ak+1][ar] = bv.y; Bs[ak+2][ar] = bv.z; Bs[ak+3][ar] = bv.w;
        __syncthreads();
        #pragma unroll
        for (int kk = 0; kk < 8; kk++) {
            float a[8], b[8];
            *(float4*)&a[0] = *(const float4*)&As[kk][ty*4];
            *(float4*)&a[4] = *(const float4*)&As[kk][64 + ty*4];
            *(float4*)&b[0] = *(const float4*)&Bs[kk][tx*4];
            *(float4*)&b[4] = *(const float4*)&Bs[kk][64 + tx*4];
            #pragma unroll
            for (int i = 0; i < 8; i++)
                #pragma unroll
                for (int j = 0; j < 8; j++) acc[i][j] += a[i] * b[j];
        }
    }

    #pragma unroll
    for (int i = 0; i < 8; i++) {
        int r = m0 + ((i < 4) ? (ty*4 + i) : (64 + ty*4 + i - 4));
        if (r >= M) continue;
        #pragma unroll
        for (int j = 0; j < 8; j++) {
            int cix = n0 + ((j < 4) ? (tx*4 + j) : (64 + tx*4 + j - 4));
            if (cix < N) store_val(C, (size_t)r * N + cix, acc[i][j] + bias[cix]);
        }
    }
}

// ================= PERSISTENT LOOP KERNEL =================
// One launch for all 100 steps; 4 grid barriers per step.
// Phase bodies are the R13-proven kernels wrapped in grid-stride work loops.
__global__ __launch_bounds__(256, 2)
void decoder_loop_kernel(const float4* __restrict__ Wih4,
                         const float4* __restrict__ Whh4,
                         const float* __restrict__ b_hh,
                         const float4* __restrict__ Ws4,
                         const float* __restrict__ v_att,
                         const float* __restrict__ W_fb,
                         const int* __restrict__ seq_len)
{
    __shared__ float sv[ATT];     // v_att   (loaded once)
    __shared__ float sfb[ATT];    // W_fb    (loaded once)
    __shared__ float pool[1024];  // per-phase scratch (lstm red / s_sm / softmax red+csm)

    int tid = threadIdx.x, warp = tid >> 5, lane = tid & 31;
    int local_sense = 0;

    for (int i = tid; i < ATT/4; i += 256) {
        ((float4*)sv)[i]  = ((const float4*)v_att)[i];
        ((float4*)sfb)[i] = ((const float4*)W_fb)[i];
    }
    __syncthreads();

    for (int n = 0; n < Nsz; n++) {
        // ---------- phase 1: LSTM recurrent GEMV + pointwise ----------
        for (int w = blockIdx.x; w < 256; w += gridDim.x) {
            int half = warp >> 2, ul = warp & 3;
            int u = w * 4 + ul;

            float acc[4][16];
            #pragma unroll
            for (int r = 0; r < 4; r++)
                #pragma unroll
                for (int b = 0; b < 16; b++) acc[r][b] = 0.0f;

            if (n > 0) {
                const float4* hprev4 = (const float4*)g_s_stk;
                if (half == 0) {
                    const float4* w0 = Wih4 + (size_t)u * (XIN/4) + 160;
                    const float4* w1 = w0 + (size_t)1024 * (XIN/4);
                    const float4* w2 = w1 + (size_t)1024 * (XIN/4);
                    const float4* w3 = w2 + (size_t)1024 * (XIN/4);
                    const float4* ctx4 = (const float4*)g_ctx_stk;
                    #pragma unroll
                    for (int it = 0; it < 4; it++) {
                        int k4c = it*32 + lane;
                        float4 a0 = __ldcs(w0 + k4c), a1 = __ldcs(w1 + k4c);
                        float4 a2 = __ldcs(w2 + k4c), a3 = __ldcs(w3 + k4c);
                        #pragma unroll
                        for (int b = 0; b < 16; b++) {
                            float4 x = ctx4[(size_t)(b*Nsz + n - 1)*(ENC/4) + k4c];
                            acc[0][b] += dot4(a0, x);
                            acc[1][b] += dot4(a1, x);
                            acc[2][b] += dot4(a2, x);
                            acc[3][b] += dot4(a3, x);
                        }
                    }
                    const float4* v0 = Whh4 + (size_t)u * (HID/4);
                    const float4* v1 = v0 + (size_t)1024 * (HID/4);
                    const float4* v2 = v1 + (size_t)1024 * (HID/4);
                    const float4* v3 = v2 + (size_t)1024 * (HID/4);
                    #pragma unroll
                    for (int it = 0; it < 2; it++) {
                        int k4 = it*32 + lane;
                        float4 a0 = __ldcs(v0 + k4), a1 = __ldcs(v1 + k4);
                        float4 a2 = __ldcs(v2 + k4), a3 = __ldcs(v3 + k4);
                        #pragma unroll
                        for (int b = 0; b < 16; b++) {
                            float4 x = hprev4[(size_t)(b*Nsz + n - 1)*(HID/4) + k4];
                            acc[0][b] += dot4(a0, x);
                            acc[1][b] += dot4(a1, x);
                            acc[2][b] += dot4(a2, x);
                            acc[3][b] += dot4(a3, x);
                        }
                    }
                } else {
                    const float4* v0 = Whh4 + (size_t)u * (HID/4);
                    const float4* v1 = v0 + (size_t)1024 * (HID/4);
                    const float4* v2 = v1 + (size_t)1024 * (HID/4);
                    const float4* v3 = v2 + (size_t)1024 * (HID/4);
                    #pragma unroll
                    for (int it = 0; it < 6; it++) {
                        int k4 = 64 + it*32 + lane;
                        float4 a0 = __ldcs(v0 + k4), a1 = __ldcs(v1 + k4);
                        float4 a2 = __ldcs(v2 + k4), a3 = __ldcs(v3 + k4);
                        #pragma unroll
                        for (int b = 0; b < 16; b++) {
                            float4 x = hprev4[(size_t)(b*Nsz + n - 1)*(HID/4) + k4];
                            acc[0][b] += dot4(a0, x);
                            acc[1][b] += dot4(a1, x);
                            acc[2][b] += dot4(a2, x);
                            acc[3][b] += dot4(a3, x);
                        }
                    }
                }
            }

            #pragma unroll
            for (int off = 16; off; off >>= 1)
                #pragma unroll
                for (int r = 0; r < 4; r++)
                    #pragma unroll
                    for (int b = 0; b < 16; b++)
                        acc[r][b] += __shfl_xor_sync(0xffffffffu, acc[r][b], off);

            float* red = pool;   // [8][64]
            if (lane == 0) {
                #pragma unroll
                for (int r = 0; r < 4; r++)
                    #pragma unroll
                    for (int b = 0; b < 16; b++)
                        red[warp*64 + r*16 + b] = acc[r][b];
            }
            __syncthreads();

            if (tid < 64) {
                int b = tid & 15, uu = tid >> 4;
                int ug = w * 4 + uu;
                const float* ge = g_gates_emb + (size_t)(b*Nsz + n) * GATES;  // incl b_ih
                float gi = red[uu*64 + 0*16 + b] + red[(4+uu)*64 + 0*16 + b] + ge[ug]       + b_hh[ug];
                float gf = red[uu*64 + 1*16 + b] + red[(4+uu)*64 + 1*16 + b] + ge[1024+ug] + b_hh[1024+ug];
                float gg = red[uu*64 + 2*16 + b] + red[(4+uu)*64 + 2*16 + b] + ge[2048+ug] + b_hh[2048+ug];
                float go = red[uu*64 + 3*16 + b] + red[(4+uu)*64 + 3*16 + b] + ge[3072+ug] + b_hh[3072+ug];
                int hi = b*HID + ug;
                float c_new = sigf(gf) * g_c[hi] + sigf(gi) * tanh_acc(gg);
                float h_new = sigf(go) * tanh_acc(c_new);
                g_c[hi] = c_new;
                g_s_stk[((size_t)b*Nsz + n)*HID + ug] = h_new;
            }
            __syncthreads();
        }
        grid_barrier(&local_sense);

        // ---------- phase 2: s_t = h(n) @ W_s^T  +  zero ctx slot n ----------
        for (int w = blockIdx.x; w < 128; w += gridDim.x) {
            int j = w * 8 + warp;   // 8 warps x 8 j-groups
            float acc[16];
            #pragma unroll
            for (int b = 0; b < 16; b++) acc[b] = 0.0f;
            const float4* wv = Ws4 + (size_t)j * (HID/4);
            const float4* h4 = (const float4*)g_s_stk;
            #pragma unroll
            for (int it = 0; it < 8; it++) {
                int k4 = it*32 + lane;
                float4 a = __ldcs(wv + k4);
                #pragma unroll
                for (int b = 0; b < 16; b++)
                    acc[b] += dot4(a, h4[(size_t)(b*Nsz + n)*(HID/4) + k4]);
            }
            #pragma unroll
            for (int off = 16; off; off >>= 1)
                #pragma unroll
                for (int b = 0; b < 16; b++)
                    acc[b] += __shfl_xor_sync(0xffffffffu, acc[b], off);
            if (lane == 0) {
                #pragma unroll
                for (int b = 0; b < 16; b++) g_s_t[b*ATT + j] = acc[b];
            }
        }
        for (int z = blockIdx.x; z < Bsz; z += gridDim.x) {
            float4* dst = (float4*)(g_ctx_stk + ((size_t)z*Nsz + n)*ENC);
            for (int i = tid; i < ENC/4; i += 256)
                dst[i] = make_float4(0,0,0,0);
        }
        grid_barrier(&local_sense);

        // ---------- phase 3: attention energies (fp16 enc_ctx, accurate tanh) ----------
        for (int w = blockIdx.x; w < 2000; w += gridDim.x) {
            int tile = w / 16, b = w % 16;     // tile 0..124
            __syncthreads();                   // protect pool reuse
            float* s_sm = pool;
            for (int i = tid; i < ATT/4; i += 256)
                ((float4*)s_sm)[i] = ((const float4*)(g_s_t + b*ATT))[i];
            __syncthreads();

            int t = tile * 8 + warp;
            float ac = g_accum[b*Tsz + t];
            const uint4* ec = (const uint4*)(g_enc_ctx + ((size_t)b*Tsz + t)*ATT);
            float sum = 0.0f;
            #pragma unroll
            for (int it = 0; it < 4; it++) {
                int k8 = it*32 + lane;
                uint4 p = ec[k8];
                int a0 = k8 * 8;
                float2 e0 = h22f2(p.x), e1 = h22f2(p.y), e2 = h22f2(p.z), e3 = h22f2(p.w);
                float e[8]  = {e0.x, e0.y, e1.x, e1.y, e2.x, e2.y, e3.x, e3.y};
                float4 s0 = *(const float4*)&s_sm[a0],  s1 = *(const float4*)&s_sm[a0+4];
                float4 v0 = *(const float4*)&sv[a0],    v1 = *(const float4*)&sv[a0+4];
                float4 f0 = *(const float4*)&sfb[a0],   f1 = *(const float4*)&sfb[a0+4];
                float sa[8] = {s0.x,s0.y,s0.z,s0.w, s1.x,s1.y,s1.z,s1.w};
                float va[8] = {v0.x,v0.y,v0.z,v0.w, v1.x,v1.y,v1.z,v1.w};
                float fa[8] = {f0.x,f0.y,f0.z,f0.w, f1.x,f1.y,f1.z,f1.w};
                #pragma unroll
                for (int jj = 0; jj < 8; jj++)
                    sum += tanh_acc(e[jj] + sa[jj] + ac*fa[jj]) * va[jj];
            }
            sum = warp_sum(sum);
            if (lane == 0) g_energies[b*Tsz + t] = sum;
        }
        grid_barrier(&local_sense);

        // ---------- phase 4: masked softmax + fertility accumulate + context ----------
        for (int w = blockIdx.x; w < 128; w += gridDim.x) {
            int tile8 = w & 7, b = w >> 3;
            int len = seq_len[b];
            float* red = pool;                       // [256]
            float4* csm = (float4*)(pool + 256);     // [128]
            const float* en = g_energies + b*Tsz;
            __syncthreads();                         // protect pool reuse

            float mx = -1e30f;
            for (int t = tid; t < len; t += 256) mx = fmaxf(mx, en[t]);
            red[tid] = mx; __syncthreads();
            for (int s = 128; s; s >>= 1) {
                if (tid < s) red[tid] = fmaxf(red[tid], red[tid + s]);
                __syncthreads();
            }
            mx = red[0]; __syncthreads();

            float sm = 0.0f;
            for (int t = tid; t < len; t += 256) sm += __expf(en[t] - mx);
            red[tid] = sm; __syncthreads();
            for (int s = 128; s; s >>= 1) {
                if (tid < s) red[tid] += red[tid + s];
                __syncthreads();
            }
            float inv = 1.0f / red[0];

            int tz = warp >> 2, dw = warp & 3;
            int d4 = dw*32 + lane;
            const float4* enc4 = (const float4*)0;   // set below via g pointer param-free path
            // enc_out fp32 pointer passed via g_s (see kernel arg repurpose) — use global symbol:
            // (we pass enc_out through a device pointer global)
            extern __device__ float4* g_enc4_ptr;
            float4 acc = make_float4(0,0,0,0);
            int t0 = tile8 * 125;
            for (int t = t0 + tz; t < t0 + 125; t += 2) {
                float wgt = (t < len) ? __expf(en[t] - mx) * inv : 0.0f;
                if (dw == 0 && lane == 0)
                    g_accum[b*Tsz + t] += wgt * g_inv_fert[b*Tsz + t] * 0.5f;
                float4 e = g_enc4_ptr[((size_t)b*Tsz + t)*(ENC/4) + d4];
                acc.x += wgt*e.x; acc.y += wgt*e.y; acc.z += wgt*e.z; acc.w += wgt*e.w;
            }
            if (tz == 1) csm[d4] = acc;
            __syncthreads();
            if (tz == 0) {
                float4 o = csm[d4];
                acc.x += o.x; acc.y += o.y; acc.z += o.z; acc.w += o.w;
                float* dst = g_ctx_stk + ((size_t)b*Nsz + n)*ENC + d4*4;
                atomicAdd(dst + 0, acc.x);
                atomicAdd(dst + 1, acc.y);
                atomicAdd(dst + 2, acc.z);
                atomicAdd(dst + 3, acc.w);
            }
            __syncthreads();
        }
        grid_barrier(&local_sense);
    }
}

// device pointer to enc_out (fp32), set once per call by a tiny kernel
__device__ float4* g_enc4_ptr;
__global__ void set_enc_ptr_kernel(const float4* enc4) {
    if (threadIdx.x == 0 && blockIdx.x == 0)
        g_enc4_ptr = (float4*)enc4;
}

// ---------------- pack readout input [s | emb | ctx] ----------------
__global__ void pack_kernel() {
    int i = blockIdx.x * blockDim.x + threadIdx.x;
    if (i >= ROWS*(ROK/4)) return;
    int r = i / (ROK/4), k4 = i % (ROK/4);
    float4 v;
    if (k4 < HID/4)            v = ((const float4*)g_s_stk)[(size_t)r*(HID/4) + k4];
    else if (k4 < (HID+EMB)/4) v = ((const float4*)g_emb)[(size_t)r*(EMB/4) + (k4 - HID/4)];
    else                       v = ((const float4*)g_ctx_stk)[(size_t)r*(ENC/4) + (k4 - (HID+EMB)/4)];
    ((float4*)g_ro_cat)[i] = v;
}

// ---------------- maxout over pairs ----------------
__global__ void maxout_kernel() {
    int i = blockIdx.x * blockDim.x + threadIdx.x;
    if (i >= ROWS*(PROJ/2)) return;
    float2 p = ((const float2*)g_ro_in)[i];
    g_readout[i] = fmaxf(p.x, p.y);
}

// ---------------- tail outputs ----------------
__global__ void tail_kernel(float* __restrict__ out) {
    int i = blockIdx.x * blockDim.x + threadIdx.x;
    if (i >= (int)TAIL_ELEMS) return;
    float v;
    if (i < Bsz*HID) {
        int b = i / HID, u = i % HID;
        v = g_s_stk[((size_t)b*Nsz + (Nsz-1))*HID + u];
    }
    else if (i < 2*Bsz*HID)               v = g_c[i - Bsz*HID];
    else if (i < 2*Bsz*HID + Bsz*ENC) {
        int j = i - 2*Bsz*HID;
        int b = j / ENC, d = j % ENC;
        v = g_ctx_stk[((size_t)b*Nsz + (Nsz-1))*ENC + d];
    } else                                v = g_accum[i - 2*Bsz*HID - Bsz*ENC];
    out[LOGITS_ELEMS + i] = v;
}

// ---------------- host launch ----------------
extern "C" void kernel_launch(void* const* d_in, const int* in_sizes, int n_in,
                              void* d_out, int out_size) {
    const float* enc_out  = (const float*)d_in[0];
    const int*   labels   = (const int*)  d_in[1];
    const int*   seq_len  = (const int*)  d_in[2];
    const float* table    = (const float*)d_in[3];
    const float* W_ih     = (const float*)d_in[4];
    const float* W_hh     = (const float*)d_in[5];
    const float* b_ih     = (const float*)d_in[6];
    const float* b_hh     = (const float*)d_in[7];
    const float* W_s      = (const float*)d_in[8];
    const float* W_enc    = (const float*)d_in[9];
    const float* b_enc    = (const float*)d_in[10];
    const float* v_att    = (const float*)d_in[11];
    const float* W_fert   = (const float*)d_in[12];
    const float* W_fb     = (const float*)d_in[13];
    const float* W_ro     = (const float*)d_in[14];
    const float* b_ro     = (const float*)d_in[15];
    const float* W_out    = (const float*)d_in[16];
    const float* b_out    = (const float*)d_in[17];
    float* out = (float*)d_out;

    __half* p_enc_ctx;
    float *p_emb, *p_gates_emb, *p_ro_cat, *p_ro_in, *p_readout;
    cudaGetSymbolAddress((void**)&p_enc_ctx,   g_enc_ctx);
    cudaGetSymbolAddress((void**)&p_emb,       g_emb);
    cudaGetSymbolAddress((void**)&p_gates_emb, g_gates_emb);
    cudaGetSymbolAddress((void**)&p_ro_cat,    g_ro_cat);
    cudaGetSymbolAddress((void**)&p_ro_in,     g_ro_in);
    cudaGetSymbolAddress((void**)&p_readout,   g_readout);

    // ---- prologue ----
    init_state_kernel<<<(INIT_ELEMS + 255)/256, 256>>>();
    set_enc_ptr_kernel<<<1, 32>>>((const float4*)enc_out);
    embed_kernel<<<(Bsz*Nsz*(EMB/4) + 255)/256, 256>>>(labels, (const float4*)table);
    gemm_tn_bias<__half><<<dim3(ATT/128, (Bsz*Tsz)/128), 256>>>(
        enc_out, ENC, W_enc, ENC, b_enc, p_enc_ctx, Bsz*Tsz, ATT, ENC);
    gemm_tn_bias<float><<<dim3(GATES/128, (ROWS + 127)/128), 256>>>(
        p_emb, EMB, W_ih, XIN, b_ih, p_gates_emb, ROWS, GATES, EMB);
    fert_kernel<<<(Bsz*Tsz*32 + 255)/256, 256>>>(
        (const float4*)enc_out, (const float4*)W_fert);

    // ---- recurrent loop: ONE persistent kernel, internal grid barriers ----
    decoder_loop_kernel<<<PERSIST_BLOCKS, 256>>>(
        (const float4*)W_ih, (const float4*)W_hh, b_hh,
        (const float4*)W_s, v_att, W_fb, seq_len);

    // ---- epilogue ----
    pack_kernel<<<(ROWS*(ROK/4) + 255)/256, 256>>>();
    gemm_tn_bias<float><<<dim3(PROJ/128, (ROWS + 127)/128), 256>>>(
        p_ro_cat, ROK, W_ro, ROK, b_ro, p_ro_in, ROWS, PROJ, ROK);
    maxout_kernel<<<(ROWS*(PROJ/2) + 255)/256, 256>>>();
    gemm_tn_bias<float><<<dim3((VOCABn + 127)/128, (ROWS + 127)/128), 256>>>(
        p_readout, PROJ/2, W_out, PROJ/2, b_out, out, ROWS, VOCABn, PROJ/2);
    tail_kernel<<<(TAIL_ELEMS + 255)/256, 256>>>(out);

    (void)in_sizes; (void)n_in; (void)out_size;
}

// round 16
// speedup vs baseline: 1.3905x; 1.3905x over previous
#include <cuda_runtime.h>
#include <cuda_fp16.h>
#include <math.h>
#include <stdint.h>

// ---------------- problem dims ----------------
#define Bsz   16
#define Tsz   1000
#define Nsz   100
#define ENC   512
#define VOCABn 10025
#define EMB   640
#define HID   1024
#define ATT   1024
#define PROJ  1024
#define XIN   (EMB+ENC)      // 1152
#define ROK   (HID+EMB+ENC)  // 2176
#define ROWS  (Bsz*Nsz)      // 1600
#define GATES (4*HID)        // 4096

#define LOGITS_ELEMS ((size_t)ROWS*VOCABn)
#define TAIL_ELEMS   (2*Bsz*HID + Bsz*ENC + Bsz*Tsz)
#define INIT_ELEMS   (Bsz*HID > Bsz*Tsz ? Bsz*HID : Bsz*Tsz)   // 16384

#define SMX_TILES 40         // softmax_ctx t-tiles (25 t each) -> 640 blocks

// ---------------- device scratch ----------------
__device__ __align__(16) float g_emb[Bsz*Nsz*EMB];
__device__ __align__(16) __half g_enc_ctx[(size_t)Bsz*Tsz*ATT];   // 32.8 MB fp16 (R10-proven)
__device__ __align__(16) float g_gates_emb[(size_t)ROWS*GATES];   // W_ih-emb part + b_ih
__device__ __align__(16) float g_inv_fert[Bsz*Tsz];
__device__ __align__(16) float g_c[Bsz*HID];
__device__ __align__(16) float g_accum[Bsz*Tsz];
__device__ __align__(16) float g_s_t[Bsz*ATT];
__device__ __align__(16) float g_energies[Bsz*Tsz];
__device__ __align__(16) float g_s_stk[(size_t)Bsz*Nsz*HID];   // h per step (h double-buffer)
__device__ __align__(16) float g_ctx_stk[(size_t)Bsz*Nsz*ENC];
__device__ __align__(16) float g_ro_cat[(size_t)ROWS*ROK];
__device__ __align__(16) float g_ro_in[(size_t)ROWS*PROJ];
__device__ __align__(16) float g_readout[(size_t)ROWS*(PROJ/2)];

// ---------------- helpers ----------------
__device__ __forceinline__ float sigf(float x) {           // exact (LSTM feedback path)
    return 1.0f / (1.0f + __expf(-x));
}
__device__ __forceinline__ float tanh_acc(float x) {       // exact (LSTM feedback path)
    float e = __expf(2.0f * x);
    return 1.0f - 2.0f / (e + 1.0f);
}
__device__ __forceinline__ float tanh_fd(float x) {        // fast-div variant (energies only)
    float e = __expf(2.0f * x);
    return 1.0f - __fdividef(2.0f, e + 1.0f);
}
__device__ __forceinline__ float warp_sum(float v) {
    #pragma unroll
    for (int off = 16; off; off >>= 1) v += __shfl_xor_sync(0xffffffffu, v, off);
    return v;
}
__device__ __forceinline__ float dot4(float4 a, float4 b) {
    return a.x*b.x + a.y*b.y + a.z*b.z + a.w*b.w;
}
__device__ __forceinline__ float2 h22f2(unsigned v) {
    __half2 h = *reinterpret_cast<__half2*>(&v);
    return __half22float2(h);
}

// ---------------- init ----------------
__global__ void init_state_kernel() {
    int i = blockIdx.x * blockDim.x + threadIdx.x;
    if (i < Bsz*HID) g_c[i] = 0.0f;
    if (i < Bsz*Tsz) g_accum[i] = 0.0f;
}

// ---------------- shifted embedding gather (float4) ----------------
__global__ void embed_kernel(const int* __restrict__ labels,
                             const float4* __restrict__ table4) {
    int i = blockIdx.x * blockDim.x + threadIdx.x;
    if (i >= Bsz*Nsz*(EMB/4)) return;
    int k4 = i % (EMB/4);
    int r  = i / (EMB/4);
    int nn = r % Nsz;
    int b  = r / Nsz;
    float4 v = make_float4(0,0,0,0);
    if (nn > 0) {
        int lab = labels[b*Nsz + nn - 1];
        v = table4[(size_t)lab*(EMB/4) + k4];
    }
    ((float4*)g_emb)[i] = v;
}

// ---------------- inv_fertility ----------------
__global__ void fert_kernel(const float4* __restrict__ enc4,
                            const float4* __restrict__ Wf4) {
    int gw   = (blockIdx.x * blockDim.x + threadIdx.x) >> 5;
    int lane = threadIdx.x & 31;
    if (gw >= Bsz*Tsz) return;
    const float4* row = enc4 + (size_t)gw * (ENC/4);
    float s = 0.0f;
    #pragma unroll
    for (int it = 0; it < 4; it++) {
        int k4 = it*32 + lane;
        s += dot4(row[k4], Wf4[k4]);
    }
    s = warp_sum(s);
    if (lane == 0) g_inv_fert[gw] = sigf(s);
}

// ---------------- SGEMM (R8-proven, + lda/ldb): C[M,N] = A@B^T + bias ----------------
__device__ __forceinline__ void store_val(float* C, size_t i, float v) { C[i] = v; }
__device__ __forceinline__ void store_val(__half* C, size_t i, float v) { C[i] = __float2half_rn(v); }

template <typename OutT>
__global__ __launch_bounds__(256)
void gemm_tn_bias(const float* __restrict__ A, int lda,
                  const float* __restrict__ Bm, int ldb,
                  const float* __restrict__ bias, OutT* __restrict__ C,
                  int M, int N, int K)
{
    __shared__ float As[8][128];
    __shared__ float Bs[8][128];
    int tid = threadIdx.x;
    int m0 = blockIdx.y * 128;
    int n0 = blockIdx.x * 128;
    int tx = tid & 15, ty = tid >> 4;

    float acc[8][8];
    #pragma unroll
    for (int i = 0; i < 8; i++)
        #pragma unroll
        for (int j = 0; j < 8; j++) acc[i][j] = 0.0f;

    int ar = tid >> 1;
    int ak = (tid & 1) * 4;

    for (int k0 = 0; k0 < K; k0 += 8) {
        float4 av = make_float4(0,0,0,0), bv = make_float4(0,0,0,0);
        int gr = m0 + ar;
        if (gr < M) av = *(const float4*)(A + (size_t)gr * lda + k0 + ak);
        int gc = n0 + ar;
        if (gc < N) bv = *(const float4*)(Bm + (size_t)gc * ldb + k0 + ak);
        __syncthreads();
        As[ak+0][ar] = av.x; As[ak+1][ar] = av.y; As[ak+2][ar] = av.z; As[ak+3][ar] = av.w;
        Bs[ak+0][ar] = bv.x; Bs[ak+1][ar] = bv.y; Bs[ak+2][ar] = bv.z; Bs[ak+3][ar] = bv.w;
        __syncthreads();
        #pragma unroll
        for (int kk = 0; kk < 8; kk++) {
            float a[8], b[8];
            *(float4*)&a[0] = *(const float4*)&As[kk][ty*4];
            *(float4*)&a[4] = *(const float4*)&As[kk][64 + ty*4];
            *(float4*)&b[0] = *(const float4*)&Bs[kk][tx*4];
            *(float4*)&b[4] = *(const float4*)&Bs[kk][64 + tx*4];
            #pragma unroll
            for (int i = 0; i < 8; i++)
                #pragma unroll
                for (int j = 0; j < 8; j++) acc[i][j] += a[i] * b[j];
        }
    }

    #pragma unroll
    for (int i = 0; i < 8; i++) {
        int r = m0 + ((i < 4) ? (ty*4 + i) : (64 + ty*4 + i - 4));
        if (r >= M) continue;
        #pragma unroll
        for (int j = 0; j < 8; j++) {
            int cix = n0 + ((j < 4) ? (tx*4 + j) : (64 + tx*4 + j - 4));
            if (cix < N) store_val(C, (size_t)r * N + cix, acc[i][j] + bias[cix]);
        }
    }
}

// ---------------- fused LSTM: recurrent-only GEMV + pointwise (R13-proven) ----------------
__global__ __launch_bounds__(256)
void lstm_fused_kernel(int n,
                       const float4* __restrict__ Wih4,
                       const float4* __restrict__ Whh4,
                       const float* __restrict__ b_hh)
{
    __shared__ float red[8][64];
    int tid = threadIdx.x, warp = tid >> 5, lane = tid & 31;
    int half = warp >> 2, ul = warp & 3;
    int u = blockIdx.x * 4 + ul;

    float acc[4][16];
    #pragma unroll
    for (int r = 0; r < 4; r++)
        #pragma unroll
        for (int b = 0; b < 16; b++) acc[r][b] = 0.0f;

    if (n > 0) {
        const float4* hprev4 = (const float4*)g_s_stk;
        if (half == 0) {
            const float4* w0 = Wih4 + (size_t)u * (XIN/4) + 160;
            const float4* w1 = w0 + (size_t)1024 * (XIN/4);
            const float4* w2 = w1 + (size_t)1024 * (XIN/4);
            const float4* w3 = w2 + (size_t)1024 * (XIN/4);
            const float4* ctx4 = (const float4*)g_ctx_stk;
            #pragma unroll
            for (int it = 0; it < 4; it++) {
                int k4c = it*32 + lane;
                float4 a0 = __ldcs(w0 + k4c), a1 = __ldcs(w1 + k4c);
                float4 a2 = __ldcs(w2 + k4c), a3 = __ldcs(w3 + k4c);
                #pragma unroll
                for (int b = 0; b < 16; b++) {
                    float4 x = ctx4[(size_t)(b*Nsz + n - 1)*(ENC/4) + k4c];
                    acc[0][b] += dot4(a0, x);
                    acc[1][b] += dot4(a1, x);
                    acc[2][b] += dot4(a2, x);
                    acc[3][b] += dot4(a3, x);
                }
            }
            const float4* v0 = Whh4 + (size_t)u * (HID/4);
            const float4* v1 = v0 + (size_t)1024 * (HID/4);
            const float4* v2 = v1 + (size_t)1024 * (HID/4);
            const float4* v3 = v2 + (size_t)1024 * (HID/4);
            #pragma unroll
            for (int it = 0; it < 2; it++) {
                int k4 = it*32 + lane;
                float4 a0 = __ldcs(v0 + k4), a1 = __ldcs(v1 + k4);
                float4 a2 = __ldcs(v2 + k4), a3 = __ldcs(v3 + k4);
                #pragma unroll
                for (int b = 0; b < 16; b++) {
                    float4 x = hprev4[(size_t)(b*Nsz + n - 1)*(HID/4) + k4];
                    acc[0][b] += dot4(a0, x);
                    acc[1][b] += dot4(a1, x);
                    acc[2][b] += dot4(a2, x);
                    acc[3][b] += dot4(a3, x);
                }
            }
        } else {
            const float4* v0 = Whh4 + (size_t)u * (HID/4);
            const float4* v1 = v0 + (size_t)1024 * (HID/4);
            const float4* v2 = v1 + (size_t)1024 * (HID/4);
            const float4* v3 = v2 + (size_t)1024 * (HID/4);
            #pragma unroll
            for (int it = 0; it < 6; it++) {
                int k4 = 64 + it*32 + lane;
                float4 a0 = __ldcs(v0 + k4), a1 = __ldcs(v1 + k4);
                float4 a2 = __ldcs(v2 + k4), a3 = __ldcs(v3 + k4);
                #pragma unroll
                for (int b = 0; b < 16; b++) {
                    float4 x = hprev4[(size_t)(b*Nsz + n - 1)*(HID/4) + k4];
                    acc[0][b] += dot4(a0, x);
                    acc[1][b] += dot4(a1, x);
                    acc[2][b] += dot4(a2, x);
                    acc[3][b] += dot4(a3, x);
                }
            }
        }
    }

    #pragma unroll
    for (int off = 16; off; off >>= 1)
        #pragma unroll
        for (int r = 0; r < 4; r++)
            #pragma unroll
            for (int b = 0; b < 16; b++)
                acc[r][b] += __shfl_xor_sync(0xffffffffu, acc[r][b], off);

    if (lane == 0) {
        #pragma unroll
        for (int r = 0; r < 4; r++)
            #pragma unroll
            for (int b = 0; b < 16; b++)
                red[warp][r*16 + b] = acc[r][b];
    }
    __syncthreads();

    if (tid < 64) {
        int b = tid & 15, uu = tid >> 4;
        int ug = blockIdx.x * 4 + uu;
        const float* ge = g_gates_emb + (size_t)(b*Nsz + n) * GATES;   // includes b_ih
        float gi = red[uu][0*16 + b] + red[4+uu][0*16 + b] + ge[ug]       + b_hh[ug];
        float gf = red[uu][1*16 + b] + red[4+uu][1*16 + b] + ge[1024+ug] + b_hh[1024+ug];
        float gg = red[uu][2*16 + b] + red[4+uu][2*16 + b] + ge[2048+ug] + b_hh[2048+ug];
        float go = red[uu][3*16 + b] + red[4+uu][3*16 + b] + ge[3072+ug] + b_hh[3072+ug];
        int hi = b*HID + ug;
        float c_new = sigf(gf) * g_c[hi] + sigf(gi) * tanh_acc(gg);
        float h_new = sigf(go) * tanh_acc(c_new);
        g_c[hi] = c_new;
        g_s_stk[((size_t)b*Nsz + n)*HID + ug] = h_new;
    }
}

// ---------------- s_t = h(n) @ W_s^T (R13 verbatim) ----------------
__global__ __launch_bounds__(128)
void s_transform_kernel(int n, const float4* __restrict__ Ws4) {
    int tid = threadIdx.x, warp = tid >> 5, lane = tid & 31;
    int j = blockIdx.x * 4 + warp;
    float acc[16];
    #pragma unroll
    for (int b = 0; b < 16; b++) acc[b] = 0.0f;
    const float4* w = Ws4 + (size_t)j * (HID/4);
    const float4* h4 = (const float4*)g_s_stk;
    #pragma unroll
    for (int it = 0; it < 8; it++) {
        int k4 = it*32 + lane;
        float4 a = __ldcs(w + k4);
        #pragma unroll
        for (int b = 0; b < 16; b++)
            acc[b] += dot4(a, h4[(size_t)(b*Nsz + n)*(HID/4) + k4]);
    }
    #pragma unroll
    for (int off = 16; off; off >>= 1)
        #pragma unroll
        for (int b = 0; b < 16; b++)
            acc[b] += __shfl_xor_sync(0xffffffffu, acc[b], off);
    if (lane == 0) {
        #pragma unroll
        for (int b = 0; b < 16; b++) g_s_t[b*ATT + j] = acc[b];
    }
}

// ---------------- attention energies (fp16 enc_ctx; fast-div tanh) ----------------
__global__ __launch_bounds__(256)
void energies_kernel(int n,
                     const float* __restrict__ v_att,
                     const float* __restrict__ W_fb) {
    int b = blockIdx.y;
    __shared__ float s_sm[ATT], v_sm[ATT], fb_sm[ATT];
    int tid = threadIdx.x;
    for (int i = tid; i < ATT/4; i += 256) {
        ((float4*)s_sm)[i]  = ((const float4*)(g_s_t + b*ATT))[i];
        ((float4*)v_sm)[i]  = ((const float4*)v_att)[i];
        ((float4*)fb_sm)[i] = ((const float4*)W_fb)[i];
    }
    if (blockIdx.x == 0) {
        for (int i = tid; i < ENC; i += 256)
            g_ctx_stk[((size_t)b*Nsz + n)*ENC + i] = 0.0f;
    }
    __syncthreads();

    int warp = tid >> 5, lane = tid & 31;
    int t = blockIdx.x * 8 + warp;
    float ac = g_accum[b*Tsz + t];
    const uint4* ec = (const uint4*)(g_enc_ctx + ((size_t)b*Tsz + t)*ATT);
    float sum = 0.0f;
    #pragma unroll
    for (int it = 0; it < 4; it++) {
        int k8 = it*32 + lane;       // uint4 = 8 fp16
        uint4 p = ec[k8];
        int a0 = k8 * 8;
        float2 e0 = h22f2(p.x), e1 = h22f2(p.y), e2 = h22f2(p.z), e3 = h22f2(p.w);
        float e[8]  = {e0.x, e0.y, e1.x, e1.y, e2.x, e2.y, e3.x, e3.y};
        float4 s0 = *(const float4*)&s_sm[a0],  s1 = *(const float4*)&s_sm[a0+4];
        float4 v0 = *(const float4*)&v_sm[a0],  v1 = *(const float4*)&v_sm[a0+4];
        float4 f0 = *(const float4*)&fb_sm[a0], f1 = *(const float4*)&fb_sm[a0+4];
        float sa[8] = {s0.x,s0.y,s0.z,s0.w, s1.x,s1.y,s1.z,s1.w};
        float va[8] = {v0.x,v0.y,v0.z,v0.w, v1.x,v1.y,v1.z,v1.w};
        float fa[8] = {f0.x,f0.y,f0.z,f0.w, f1.x,f1.y,f1.z,f1.w};
        #pragma unroll
        for (int jj = 0; jj < 8; jj++)
            sum += tanh_fd(e[jj] + sa[jj] + ac*fa[jj]) * va[jj];
    }
    sum = warp_sum(sum);
    if (lane == 0) g_energies[b*Tsz + t] = sum;
}

// ---------------- fused masked softmax + fertility accumulate + context ----------------
// 40 t-tiles (25 t each) x 16 b = 640 blocks: fixes the 128-block occupancy hole.
__global__ __launch_bounds__(256)
void softmax_ctx_kernel(int n, const int* __restrict__ seq_len,
                        const float4* __restrict__ enc4) {
    int b = blockIdx.y;
    int tid = threadIdx.x;
    int len = seq_len[b];
    __shared__ float red[256];
    __shared__ float4 csm[ENC/4];
    const float* en = g_energies + b*Tsz;

    float mx = -1e30f;
    for (int t = tid; t < len; t += 256) mx = fmaxf(mx, en[t]);
    red[tid] = mx; __syncthreads();
    for (int s = 128; s; s >>= 1) {
        if (tid < s) red[tid] = fmaxf(red[tid], red[tid + s]);
        __syncthreads();
    }
    mx = red[0]; __syncthreads();

    float sm = 0.0f;
    for (int t = tid; t < len; t += 256) sm += __expf(en[t] - mx);
    red[tid] = sm; __syncthreads();
    for (int s = 128; s; s >>= 1) {
        if (tid < s) red[tid] += red[tid + s];
        __syncthreads();
    }
    float inv = 1.0f / red[0];

    int warp = tid >> 5, lane = tid & 31;
    int tz = warp >> 2, dw = warp & 3;
    int d4 = dw*32 + lane;
    float4 acc = make_float4(0,0,0,0);
    int t0 = blockIdx.x * 25;             // 40 tiles x 25 t
    for (int t = t0 + tz; t < t0 + 25; t += 2) {
        float w = (t < len) ? __expf(en[t] - mx) * inv : 0.0f;
        if (dw == 0 && lane == 0)
            g_accum[b*Tsz + t] += w * g_inv_fert[b*Tsz + t] * 0.5f;
        float4 e = enc4[((size_t)b*Tsz + t)*(ENC/4) + d4];
        acc.x += w*e.x; acc.y += w*e.y; acc.z += w*e.z; acc.w += w*e.w;
    }
    if (tz == 1) csm[d4] = acc;
    __syncthreads();
    if (tz == 0) {
        float4 o = csm[d4];
        acc.x += o.x; acc.y += o.y; acc.z += o.z; acc.w += o.w;
        float* dst = g_ctx_stk + ((size_t)b*Nsz + n)*ENC + d4*4;
        atomicAdd(dst + 0, acc.x);
        atomicAdd(dst + 1, acc.y);
        atomicAdd(dst + 2, acc.z);
        atomicAdd(dst + 3, acc.w);
    }
}

// ---------------- pack readout input [s | emb | ctx] ----------------
__global__ void pack_kernel() {
    int i = blockIdx.x * blockDim.x + threadIdx.x;
    if (i >= ROWS*(ROK/4)) return;
    int r = i / (ROK/4), k4 = i % (ROK/4);
    float4 v;
    if (k4 < HID/4)            v = ((const float4*)g_s_stk)[(size_t)r*(HID/4) + k4];
    else if (k4 < (HID+EMB)/4) v = ((const float4*)g_emb)[(size_t)r*(EMB/4) + (k4 - HID/4)];
    else                       v = ((const float4*)g_ctx_stk)[(size_t)r*(ENC/4) + (k4 - (HID+EMB)/4)];
    ((float4*)g_ro_cat)[i] = v;
}

// ---------------- maxout over pairs ----------------
__global__ void maxout_kernel() {
    int i = blockIdx.x * blockDim.x + threadIdx.x;
    if (i >= ROWS*(PROJ/2)) return;
    float2 p = ((const float2*)g_ro_in)[i];
    g_readout[i] = fmaxf(p.x, p.y);
}

// ---------------- tail outputs ----------------
__global__ void tail_kernel(float* __restrict__ out) {
    int i = blockIdx.x * blockDim.x + threadIdx.x;
    if (i >= (int)TAIL_ELEMS) return;
    float v;
    if (i < Bsz*HID) {
        int b = i / HID, u = i % HID;
        v = g_s_stk[((size_t)b*Nsz + (Nsz-1))*HID + u];
    }
    else if (i < 2*Bsz*HID)               v = g_c[i - Bsz*HID];
    else if (i < 2*Bsz*HID + Bsz*ENC) {
        int j = i - 2*Bsz*HID;
        int b = j / ENC, d = j % ENC;
        v = g_ctx_stk[((size_t)b*Nsz + (Nsz-1))*ENC + d];
    } else                                v = g_accum[i - 2*Bsz*HID - Bsz*ENC];
    out[LOGITS_ELEMS + i] = v;
}

// ---------------- host launch ----------------
extern "C" void kernel_launch(void* const* d_in, const int* in_sizes, int n_in,
                              void* d_out, int out_size) {
    const float* enc_out  = (const float*)d_in[0];
    const int*   labels   = (const int*)  d_in[1];
    const int*   seq_len  = (const int*)  d_in[2];
    const float* table    = (const float*)d_in[3];
    const float* W_ih     = (const float*)d_in[4];
    const float* W_hh     = (const float*)d_in[5];
    const float* b_ih     = (const float*)d_in[6];
    const float* b_hh     = (const float*)d_in[7];
    const float* W_s      = (const float*)d_in[8];
    const float* W_enc    = (const float*)d_in[9];
    const float* b_enc    = (const float*)d_in[10];
    const float* v_att    = (const float*)d_in[11];
    const float* W_fert   = (const float*)d_in[12];
    const float* W_fb     = (const float*)d_in[13];
    const float* W_ro     = (const float*)d_in[14];
    const float* b_ro     = (const float*)d_in[15];
    const float* W_out    = (const float*)d_in[16];
    const float* b_out    = (const float*)d_in[17];
    float* out = (float*)d_out;

    __half* p_enc_ctx;
    float *p_emb, *p_gates_emb, *p_ro_cat, *p_ro_in, *p_readout;
    cudaGetSymbolAddress((void**)&p_enc_ctx,   g_enc_ctx);
    cudaGetSymbolAddress((void**)&p_emb,       g_emb);
    cudaGetSymbolAddress((void**)&p_gates_emb, g_gates_emb);
    cudaGetSymbolAddress((void**)&p_ro_cat,    g_ro_cat);
    cudaGetSymbolAddress((void**)&p_ro_in,     g_ro_in);
    cudaGetSymbolAddress((void**)&p_readout,   g_readout);

    // ---- prologue ----
    init_state_kernel<<<(INIT_ELEMS + 255)/256, 256>>>();
    embed_kernel<<<(Bsz*Nsz*(EMB/4) + 255)/256, 256>>>(labels, (const float4*)table);
    gemm_tn_bias<__half><<<dim3(ATT/128, (Bsz*Tsz)/128), 256>>>(
        enc_out, ENC, W_enc, ENC, b_enc, p_enc_ctx, Bsz*Tsz, ATT, ENC);
    gemm_tn_bias<float><<<dim3(GATES/128, (ROWS + 127)/128), 256>>>(
        p_emb, EMB, W_ih, XIN, b_ih, p_gates_emb, ROWS, GATES, EMB);
    fert_kernel<<<(Bsz*Tsz*32 + 255)/256, 256>>>(
        (const float4*)enc_out, (const float4*)W_fert);

    // ---- recurrent loop: 4 kernels/step ----
    for (int n = 0; n < Nsz; n++) {
        lstm_fused_kernel<<<256, 256>>>(n, (const float4*)W_ih, (const float4*)W_hh, b_hh);
        s_transform_kernel<<<256, 128>>>(n, (const float4*)W_s);
        energies_kernel<<<dim3(125, Bsz), 256>>>(n, v_att, W_fb);
        softmax_ctx_kernel<<<dim3(SMX_TILES, Bsz), 256>>>(n, seq_len, (const float4*)enc_out);
    }

    // ---- epilogue ----
    pack_kernel<<<(ROWS*(ROK/4) + 255)/256, 256>>>();
    gemm_tn_bias<float><<<dim3(PROJ/128, (ROWS + 127)/128), 256>>>(
        p_ro_cat, ROK, W_ro, ROK, b_ro, p_ro_in, ROWS, PROJ, ROK);
    maxout_kernel<<<(ROWS*(PROJ/2) + 255)/256, 256>>>();
    gemm_tn_bias<float><<<dim3((VOCABn + 127)/128, (ROWS + 127)/128), 256>>>(
        p_readout, PROJ/2, W_out, PROJ/2, b_out, out, ROWS, VOCABn, PROJ/2);
    tail_kernel<<<(TAIL_ELEMS + 255)/256, 256>>>(out);

    (void)in_sizes; (void)n_in; (void)out_size;
}

// round 17
// speedup vs baseline: 1.3946x; 1.0030x over previous
#include <cuda_runtime.h>
#include <cuda_fp16.h>
#include <math.h>
#include <stdint.h>

// ---------------- problem dims ----------------
#define Bsz   16
#define Tsz   1000
#define Nsz   100
#define ENC   512
#define VOCABn 10025
#define EMB   640
#define HID   1024
#define ATT   1024
#define PROJ  1024
#define XIN   (EMB+ENC)      // 1152
#define ROK   (HID+EMB+ENC)  // 2176
#define ROWS  (Bsz*Nsz)      // 1600
#define GATES (4*HID)        // 4096

#define LOGITS_ELEMS ((size_t)ROWS*VOCABn)
#define TAIL_ELEMS   (2*Bsz*HID + Bsz*ENC + Bsz*Tsz)
#define INIT_ELEMS   (Bsz*HID > Bsz*Tsz ? Bsz*HID : Bsz*Tsz)   // 16384

#define SMX_TILES 40         // softmax_ctx t-tiles (25 t each) -> 640 blocks (R16-proven)

// ---------------- device scratch ----------------
__device__ __align__(16) float g_emb[Bsz*Nsz*EMB];
__device__ __align__(16) __half g_enc_ctx[(size_t)Bsz*Tsz*ATT];   // 32.8 MB fp16 (R10-proven)
__device__ __align__(16) float g_gates_emb[(size_t)ROWS*GATES];   // W_ih-emb part + b_ih
__device__ __align__(16) float g_inv_fert[Bsz*Tsz];
__device__ __align__(16) float g_c[Bsz*HID];
__device__ __align__(16) float g_accum[Bsz*Tsz];
__device__ __align__(16) float g_s_t[Bsz*ATT];
__device__ __align__(16) float g_energies[Bsz*Tsz];
__device__ __align__(16) float g_s_stk[(size_t)Bsz*Nsz*HID];   // h per step (h double-buffer)
__device__ __align__(16) float g_ctx_stk[(size_t)Bsz*Nsz*ENC];
__device__ __align__(16) float g_ro_cat[(size_t)ROWS*ROK];
__device__ __align__(16) float g_ro_in[(size_t)ROWS*PROJ];
__device__ __align__(16) float g_readout[(size_t)ROWS*(PROJ/2)];

// ---------------- helpers ----------------
__device__ __forceinline__ float sigf(float x) {           // exact (LSTM feedback path)
    return 1.0f / (1.0f + __expf(-x));
}
__device__ __forceinline__ float tanh_acc(float x) {       // exact (LSTM feedback path)
    float e = __expf(2.0f * x);
    return 1.0f - 2.0f / (e + 1.0f);
}
__device__ __forceinline__ float tanh_hw(float x) {        // HW tanh (energies only; retested)
    float y;
    asm("tanh.approx.f32 %0, %1;" : "=f"(y) : "f"(x));
    return y;
}
__device__ __forceinline__ float warp_sum(float v) {
    #pragma unroll
    for (int off = 16; off; off >>= 1) v += __shfl_xor_sync(0xffffffffu, v, off);
    return v;
}
__device__ __forceinline__ float dot4(float4 a, float4 b) {
    return a.x*b.x + a.y*b.y + a.z*b.z + a.w*b.w;
}
__device__ __forceinline__ float2 h22f2(unsigned v) {
    __half2 h = *reinterpret_cast<__half2*>(&v);
    return __half22float2(h);
}

// ---------------- init ----------------
__global__ void init_state_kernel() {
    int i = blockIdx.x * blockDim.x + threadIdx.x;
    if (i < Bsz*HID) g_c[i] = 0.0f;
    if (i < Bsz*Tsz) g_accum[i] = 0.0f;
}

// ---------------- shifted embedding gather (float4) ----------------
__global__ void embed_kernel(const int* __restrict__ labels,
                             const float4* __restrict__ table4) {
    int i = blockIdx.x * blockDim.x + threadIdx.x;
    if (i >= Bsz*Nsz*(EMB/4)) return;
    int k4 = i % (EMB/4);
    int r  = i / (EMB/4);
    int nn = r % Nsz;
    int b  = r / Nsz;
    float4 v = make_float4(0,0,0,0);
    if (nn > 0) {
        int lab = labels[b*Nsz + nn - 1];
        v = table4[(size_t)lab*(EMB/4) + k4];
    }
    ((float4*)g_emb)[i] = v;
}

// ---------------- inv_fertility ----------------
__global__ void fert_kernel(const float4* __restrict__ enc4,
                            const float4* __restrict__ Wf4) {
    int gw   = (blockIdx.x * blockDim.x + threadIdx.x) >> 5;
    int lane = threadIdx.x & 31;
    if (gw >= Bsz*Tsz) return;
    const float4* row = enc4 + (size_t)gw * (ENC/4);
    float s = 0.0f;
    #pragma unroll
    for (int it = 0; it < 4; it++) {
        int k4 = it*32 + lane;
        s += dot4(row[k4], Wf4[k4]);
    }
    s = warp_sum(s);
    if (lane == 0) g_inv_fert[gw] = sigf(s);
}

// ---------------- SGEMM (R8-proven, + lda/ldb): C[M,N] = A@B^T + bias ----------------
__device__ __forceinline__ void store_val(float* C, size_t i, float v) { C[i] = v; }
__device__ __forceinline__ void store_val(__half* C, size_t i, float v) { C[i] = __float2half_rn(v); }

template <typename OutT>
__global__ __launch_bounds__(256)
void gemm_tn_bias(const float* __restrict__ A, int lda,
                  const float* __restrict__ Bm, int ldb,
                  const float* __restrict__ bias, OutT* __restrict__ C,
                  int M, int N, int K)
{
    __shared__ float As[8][128];
    __shared__ float Bs[8][128];
    int tid = threadIdx.x;
    int m0 = blockIdx.y * 128;
    int n0 = blockIdx.x * 128;
    int tx = tid & 15, ty = tid >> 4;

    float acc[8][8];
    #pragma unroll
    for (int i = 0; i < 8; i++)
        #pragma unroll
        for (int j = 0; j < 8; j++) acc[i][j] = 0.0f;

    int ar = tid >> 1;
    int ak = (tid & 1) * 4;

    for (int k0 = 0; k0 < K; k0 += 8) {
        float4 av = make_float4(0,0,0,0), bv = make_float4(0,0,0,0);
        int gr = m0 + ar;
        if (gr < M) av = *(const float4*)(A + (size_t)gr * lda + k0 + ak);
        int gc = n0 + ar;
        if (gc < N) bv = *(const float4*)(Bm + (size_t)gc * ldb + k0 + ak);
        __syncthreads();
        As[ak+0][ar] = av.x; As[ak+1][ar] = av.y; As[ak+2][ar] = av.z; As[ak+3][ar] = av.w;
        Bs[ak+0][ar] = bv.x; Bs[ak+1][ar] = bv.y; Bs[ak+2][ar] = bv.z; Bs[ak+3][ar] = bv.w;
        __syncthreads();
        #pragma unroll
        for (int kk = 0; kk < 8; kk++) {
            float a[8], b[8];
            *(float4*)&a[0] = *(const float4*)&As[kk][ty*4];
            *(float4*)&a[4] = *(const float4*)&As[kk][64 + ty*4];
            *(float4*)&b[0] = *(const float4*)&Bs[kk][tx*4];
            *(float4*)&b[4] = *(const float4*)&Bs[kk][64 + tx*4];
            #pragma unroll
            for (int i = 0; i < 8; i++)
                #pragma unroll
                for (int j = 0; j < 8; j++) acc[i][j] += a[i] * b[j];
        }
    }

    #pragma unroll
    for (int i = 0; i < 8; i++) {
        int r = m0 + ((i < 4) ? (ty*4 + i) : (64 + ty*4 + i - 4));
        if (r >= M) continue;
        #pragma unroll
        for (int j = 0; j < 8; j++) {
            int cix = n0 + ((j < 4) ? (tx*4 + j) : (64 + tx*4 + j - 4));
            if (cix < N) store_val(C, (size_t)r * N + cix, acc[i][j] + bias[cix]);
        }
    }
}

// ---------------- fused LSTM: recurrent-only GEMV + pointwise (R13-proven) ----------------
__global__ __launch_bounds__(256)
void lstm_fused_kernel(int n,
                       const float4* __restrict__ Wih4,
                       const float4* __restrict__ Whh4,
                       const float* __restrict__ b_hh)
{
    __shared__ float red[8][64];
    int tid = threadIdx.x, warp = tid >> 5, lane = tid & 31;
    int half = warp >> 2, ul = warp & 3;
    int u = blockIdx.x * 4 + ul;

    float acc[4][16];
    #pragma unroll
    for (int r = 0; r < 4; r++)
        #pragma unroll
        for (int b = 0; b < 16; b++) acc[r][b] = 0.0f;

    if (n > 0) {
        const float4* hprev4 = (const float4*)g_s_stk;
        if (half == 0) {
            const float4* w0 = Wih4 + (size_t)u * (XIN/4) + 160;
            const float4* w1 = w0 + (size_t)1024 * (XIN/4);
            const float4* w2 = w1 + (size_t)1024 * (XIN/4);
            const float4* w3 = w2 + (size_t)1024 * (XIN/4);
            const float4* ctx4 = (const float4*)g_ctx_stk;
            #pragma unroll
            for (int it = 0; it < 4; it++) {
                int k4c = it*32 + lane;
                float4 a0 = __ldcs(w0 + k4c), a1 = __ldcs(w1 + k4c);
                float4 a2 = __ldcs(w2 + k4c), a3 = __ldcs(w3 + k4c);
                #pragma unroll
                for (int b = 0; b < 16; b++) {
                    float4 x = ctx4[(size_t)(b*Nsz + n - 1)*(ENC/4) + k4c];
                    acc[0][b] += dot4(a0, x);
                    acc[1][b] += dot4(a1, x);
                    acc[2][b] += dot4(a2, x);
                    acc[3][b] += dot4(a3, x);
                }
            }
            const float4* v0 = Whh4 + (size_t)u * (HID/4);
            const float4* v1 = v0 + (size_t)1024 * (HID/4);
            const float4* v2 = v1 + (size_t)1024 * (HID/4);
            const float4* v3 = v2 + (size_t)1024 * (HID/4);
            #pragma unroll
            for (int it = 0; it < 2; it++) {
                int k4 = it*32 + lane;
                float4 a0 = __ldcs(v0 + k4), a1 = __ldcs(v1 + k4);
                float4 a2 = __ldcs(v2 + k4), a3 = __ldcs(v3 + k4);
                #pragma unroll
                for (int b = 0; b < 16; b++) {
                    float4 x = hprev4[(size_t)(b*Nsz + n - 1)*(HID/4) + k4];
                    acc[0][b] += dot4(a0, x);
                    acc[1][b] += dot4(a1, x);
                    acc[2][b] += dot4(a2, x);
                    acc[3][b] += dot4(a3, x);
                }
            }
        } else {
            const float4* v0 = Whh4 + (size_t)u * (HID/4);
            const float4* v1 = v0 + (size_t)1024 * (HID/4);
            const float4* v2 = v1 + (size_t)1024 * (HID/4);
            const float4* v3 = v2 + (size_t)1024 * (HID/4);
            #pragma unroll
            for (int it = 0; it < 6; it++) {
                int k4 = 64 + it*32 + lane;
                float4 a0 = __ldcs(v0 + k4), a1 = __ldcs(v1 + k4);
                float4 a2 = __ldcs(v2 + k4), a3 = __ldcs(v3 + k4);
                #pragma unroll
                for (int b = 0; b < 16; b++) {
                    float4 x = hprev4[(size_t)(b*Nsz + n - 1)*(HID/4) + k4];
                    acc[0][b] += dot4(a0, x);
                    acc[1][b] += dot4(a1, x);
                    acc[2][b] += dot4(a2, x);
                    acc[3][b] += dot4(a3, x);
                }
            }
        }
    }

    #pragma unroll
    for (int off = 16; off; off >>= 1)
        #pragma unroll
        for (int r = 0; r < 4; r++)
            #pragma unroll
            for (int b = 0; b < 16; b++)
                acc[r][b] += __shfl_xor_sync(0xffffffffu, acc[r][b], off);

    if (lane == 0) {
        #pragma unroll
        for (int r = 0; r < 4; r++)
            #pragma unroll
            for (int b = 0; b < 16; b++)
                red[warp][r*16 + b] = acc[r][b];
    }
    __syncthreads();

    if (tid < 64) {
        int b = tid & 15, uu = tid >> 4;
        int ug = blockIdx.x * 4 + uu;
        const float* ge = g_gates_emb + (size_t)(b*Nsz + n) * GATES;   // includes b_ih
        float gi = red[uu][0*16 + b] + red[4+uu][0*16 + b] + ge[ug]       + b_hh[ug];
        float gf = red[uu][1*16 + b] + red[4+uu][1*16 + b] + ge[1024+ug] + b_hh[1024+ug];
        float gg = red[uu][2*16 + b] + red[4+uu][2*16 + b] + ge[2048+ug] + b_hh[2048+ug];
        float go = red[uu][3*16 + b] + red[4+uu][3*16 + b] + ge[3072+ug] + b_hh[3072+ug];
        int hi = b*HID + ug;
        float c_new = sigf(gf) * g_c[hi] + sigf(gi) * tanh_acc(gg);
        float h_new = sigf(go) * tanh_acc(c_new);
        g_c[hi] = c_new;
        g_s_stk[((size_t)b*Nsz + n)*HID + ug] = h_new;
    }
}

// ---------------- s_t = h(n) @ W_s^T (R13 verbatim) ----------------
__global__ __launch_bounds__(128)
void s_transform_kernel(int n, const float4* __restrict__ Ws4) {
    int tid = threadIdx.x, warp = tid >> 5, lane = tid & 31;
    int j = blockIdx.x * 4 + warp;
    float acc[16];
    #pragma unroll
    for (int b = 0; b < 16; b++) acc[b] = 0.0f;
    const float4* w = Ws4 + (size_t)j * (HID/4);
    const float4* h4 = (const float4*)g_s_stk;
    #pragma unroll
    for (int it = 0; it < 8; it++) {
        int k4 = it*32 + lane;
        float4 a = __ldcs(w + k4);
        #pragma unroll
        for (int b = 0; b < 16; b++)
            acc[b] += dot4(a, h4[(size_t)(b*Nsz + n)*(HID/4) + k4]);
    }
    #pragma unroll
    for (int off = 16; off; off >>= 1)
        #pragma unroll
        for (int b = 0; b < 16; b++)
            acc[b] += __shfl_xor_sync(0xffffffffu, acc[b], off);
    if (lane == 0) {
        #pragma unroll
        for (int b = 0; b < 16; b++) g_s_t[b*ATT + j] = acc[b];
    }
}

// ---------------- attention energies (fp16 enc_ctx; HW tanh) ----------------
__global__ __launch_bounds__(256)
void energies_kernel(int n,
                     const float* __restrict__ v_att,
                     const float* __restrict__ W_fb) {
    int b = blockIdx.y;
    __shared__ float s_sm[ATT], v_sm[ATT], fb_sm[ATT];
    int tid = threadIdx.x;
    for (int i = tid; i < ATT/4; i += 256) {
        ((float4*)s_sm)[i]  = ((const float4*)(g_s_t + b*ATT))[i];
        ((float4*)v_sm)[i]  = ((const float4*)v_att)[i];
        ((float4*)fb_sm)[i] = ((const float4*)W_fb)[i];
    }
    if (blockIdx.x == 0) {
        for (int i = tid; i < ENC; i += 256)
            g_ctx_stk[((size_t)b*Nsz + n)*ENC + i] = 0.0f;
    }
    __syncthreads();

    int warp = tid >> 5, lane = tid & 31;
    int t = blockIdx.x * 8 + warp;
    float ac = g_accum[b*Tsz + t];
    const uint4* ec = (const uint4*)(g_enc_ctx + ((size_t)b*Tsz + t)*ATT);
    float sum = 0.0f;
    #pragma unroll
    for (int it = 0; it < 4; it++) {
        int k8 = it*32 + lane;       // uint4 = 8 fp16
        uint4 p = ec[k8];
        int a0 = k8 * 8;
        float2 e0 = h22f2(p.x), e1 = h22f2(p.y), e2 = h22f2(p.z), e3 = h22f2(p.w);
        float e[8]  = {e0.x, e0.y, e1.x, e1.y, e2.x, e2.y, e3.x, e3.y};
        float4 s0 = *(const float4*)&s_sm[a0],  s1 = *(const float4*)&s_sm[a0+4];
        float4 v0 = *(const float4*)&v_sm[a0],  v1 = *(const float4*)&v_sm[a0+4];
        float4 f0 = *(const float4*)&fb_sm[a0], f1 = *(const float4*)&fb_sm[a0+4];
        float sa[8] = {s0.x,s0.y,s0.z,s0.w, s1.x,s1.y,s1.z,s1.w};
        float va[8] = {v0.x,v0.y,v0.z,v0.w, v1.x,v1.y,v1.z,v1.w};
        float fa[8] = {f0.x,f0.y,f0.z,f0.w, f1.x,f1.y,f1.z,f1.w};
        #pragma unroll
        for (int jj = 0; jj < 8; jj++)
            sum += tanh_hw(fmaf(ac, fa[jj], e[jj] + sa[jj])) * va[jj];
    }
    sum = warp_sum(sum);
    if (lane == 0) g_energies[b*Tsz + t] = sum;
}

// ---------------- fused masked softmax + fertility accumulate + context (R16-proven) ----------------
__global__ __launch_bounds__(256)
void softmax_ctx_kernel(int n, const int* __restrict__ seq_len,
                        const float4* __restrict__ enc4) {
    int b = blockIdx.y;
    int tid = threadIdx.x;
    int len = seq_len[b];
    __shared__ float red[256];
    __shared__ float4 csm[ENC/4];
    const float* en = g_energies + b*Tsz;

    float mx = -1e30f;
    for (int t = tid; t < len; t += 256) mx = fmaxf(mx, en[t]);
    red[tid] = mx; __syncthreads();
    for (int s = 128; s; s >>= 1) {
        if (tid < s) red[tid] = fmaxf(red[tid], red[tid + s]);
        __syncthreads();
    }
    mx = red[0]; __syncthreads();

    float sm = 0.0f;
    for (int t = tid; t < len; t += 256) sm += __expf(en[t] - mx);
    red[tid] = sm; __syncthreads();
    for (int s = 128; s; s >>= 1) {
        if (tid < s) red[tid] += red[tid + s];
        __syncthreads();
    }
    float inv = 1.0f / red[0];

    int warp = tid >> 5, lane = tid & 31;
    int tz = warp >> 2, dw = warp & 3;
    int d4 = dw*32 + lane;
    float4 acc = make_float4(0,0,0,0);
    int t0 = blockIdx.x * 25;             // 40 tiles x 25 t
    for (int t = t0 + tz; t < t0 + 25; t += 2) {
        float w = (t < len) ? __expf(en[t] - mx) * inv : 0.0f;
        if (dw == 0 && lane == 0)
            g_accum[b*Tsz + t] += w * g_inv_fert[b*Tsz + t] * 0.5f;
        float4 e = enc4[((size_t)b*Tsz + t)*(ENC/4) + d4];
        acc.x += w*e.x; acc.y += w*e.y; acc.z += w*e.z; acc.w += w*e.w;
    }
    if (tz == 1) csm[d4] = acc;
    __syncthreads();
    if (tz == 0) {
        float4 o = csm[d4];
        acc.x += o.x; acc.y += o.y; acc.z += o.z; acc.w += o.w;
        float* dst = g_ctx_stk + ((size_t)b*Nsz + n)*ENC + d4*4;
        atomicAdd(dst + 0, acc.x);
        atomicAdd(dst + 1, acc.y);
        atomicAdd(dst + 2, acc.z);
        atomicAdd(dst + 3, acc.w);
    }
}

// ---------------- pack readout input [s | emb | ctx] ----------------
__global__ void pack_kernel() {
    int i = blockIdx.x * blockDim.x + threadIdx.x;
    if (i >= ROWS*(ROK/4)) return;
    int r = i / (ROK/4), k4 = i % (ROK/4);
    float4 v;
    if (k4 < HID/4)            v = ((const float4*)g_s_stk)[(size_t)r*(HID/4) + k4];
    else if (k4 < (HID+EMB)/4) v = ((const float4*)g_emb)[(size_t)r*(EMB/4) + (k4 - HID/4)];
    else                       v = ((const float4*)g_ctx_stk)[(size_t)r*(ENC/4) + (k4 - (HID+EMB)/4)];
    ((float4*)g_ro_cat)[i] = v;
}

// ---------------- maxout over pairs ----------------
__global__ void maxout_kernel() {
    int i = blockIdx.x * blockDim.x + threadIdx.x;
    if (i >= ROWS*(PROJ/2)) return;
    float2 p = ((const float2*)g_ro_in)[i];
    g_readout[i] = fmaxf(p.x, p.y);
}

// ---------------- tail outputs ----------------
__global__ void tail_kernel(float* __restrict__ out) {
    int i = blockIdx.x * blockDim.x + threadIdx.x;
    if (i >= (int)TAIL_ELEMS) return;
    float v;
    if (i < Bsz*HID) {
        int b = i / HID, u = i % HID;
        v = g_s_stk[((size_t)b*Nsz + (Nsz-1))*HID + u];
    }
    else if (i < 2*Bsz*HID)               v = g_c[i - Bsz*HID];
    else if (i < 2*Bsz*HID + Bsz*ENC) {
        int j = i - 2*Bsz*HID;
        int b = j / ENC, d = j % ENC;
        v = g_ctx_stk[((size_t)b*Nsz + (Nsz-1))*ENC + d];
    } else                                v = g_accum[i - 2*Bsz*HID - Bsz*ENC];
    out[LOGITS_ELEMS + i] = v;
}

// ---------------- host launch ----------------
extern "C" void kernel_launch(void* const* d_in, const int* in_sizes, int n_in,
                              void* d_out, int out_size) {
    const float* enc_out  = (const float*)d_in[0];
    const int*   labels   = (const int*)  d_in[1];
    const int*   seq_len  = (const int*)  d_in[2];
    const float* table    = (const float*)d_in[3];
    const float* W_ih     = (const float*)d_in[4];
    const float* W_hh     = (const float*)d_in[5];
    const float* b_ih     = (const float*)d_in[6];
    const float* b_hh     = (const float*)d_in[7];
    const float* W_s      = (const float*)d_in[8];
    const float* W_enc    = (const float*)d_in[9];
    const float* b_enc    = (const float*)d_in[10];
    const float* v_att    = (const float*)d_in[11];
    const float* W_fert   = (const float*)d_in[12];
    const float* W_fb     = (const float*)d_in[13];
    const float* W_ro     = (const float*)d_in[14];
    const float* b_ro     = (const float*)d_in[15];
    const float* W_out    = (const float*)d_in[16];
    const float* b_out    = (const float*)d_in[17];
    float* out = (float*)d_out;

    __half* p_enc_ctx;
    float *p_emb, *p_gates_emb, *p_ro_cat, *p_ro_in, *p_readout;
    cudaGetSymbolAddress((void**)&p_enc_ctx,   g_enc_ctx);
    cudaGetSymbolAddress((void**)&p_emb,       g_emb);
    cudaGetSymbolAddress((void**)&p_gates_emb, g_gates_emb);
    cudaGetSymbolAddress((void**)&p_ro_cat,    g_ro_cat);
    cudaGetSymbolAddress((void**)&p_ro_in,     g_ro_in);
    cudaGetSymbolAddress((void**)&p_readout,   g_readout);

    // ---- prologue ----
    init_state_kernel<<<(INIT_ELEMS + 255)/256, 256>>>();
    embed_kernel<<<(Bsz*Nsz*(EMB/4) + 255)/256, 256>>>(labels, (const float4*)table);
    gemm_tn_bias<__half><<<dim3(ATT/128, (Bsz*Tsz)/128), 256>>>(
        enc_out, ENC, W_enc, ENC, b_enc, p_enc_ctx, Bsz*Tsz, ATT, ENC);
    gemm_tn_bias<float><<<dim3(GATES/128, (ROWS + 127)/128), 256>>>(
        p_emb, EMB, W_ih, XIN, b_ih, p_gates_emb, ROWS, GATES, EMB);
    fert_kernel<<<(Bsz*Tsz*32 + 255)/256, 256>>>(
        (const float4*)enc_out, (const float4*)W_fert);

    // ---- recurrent loop: 4 kernels/step ----
    for (int n = 0; n < Nsz; n++) {
        lstm_fused_kernel<<<256, 256>>>(n, (const float4*)W_ih, (const float4*)W_hh, b_hh);
        s_transform_kernel<<<256, 128>>>(n, (const float4*)W_s);
        energies_kernel<<<dim3(125, Bsz), 256>>>(n, v_att, W_fb);
        softmax_ctx_kernel<<<dim3(SMX_TILES, Bsz), 256>>>(n, seq_len, (const float4*)enc_out);
    }

    // ---- epilogue ----
    pack_kernel<<<(ROWS*(ROK/4) + 255)/256, 256>>>();
    gemm_tn_bias<float><<<dim3(PROJ/128, (ROWS + 127)/128), 256>>>(
        p_ro_cat, ROK, W_ro, ROK, b_ro, p_ro_in, ROWS, PROJ, ROK);
    maxout_kernel<<<(ROWS*(PROJ/2) + 255)/256, 256>>>();
    gemm_tn_bias<float><<<dim3((VOCABn + 127)/128, (ROWS + 127)/128), 256>>>(
        p_readout, PROJ/2, W_out, PROJ/2, b_out, out, ROWS, VOCABn, PROJ/2);
    tail_kernel<<<(TAIL_ELEMS + 255)/256, 256>>>(out);

    (void)in_sizes; (void)n_in; (void)out_size;
}